// round 6
// baseline (speedup 1.0000x reference)
#include <cuda_runtime.h>
#include <cstdint>
#include <math.h>

#define BB 8
#define NN 2048
#define MM 2048
#define DD 256

#define TPB 256
#define BN  64                  // src rows per CTA
#define BMT 64                  // dst rows per m-tile
#define KC  32
#define NMT (MM / BMT)          // 32
#define NCHUNK (DD / KC)        // 8
#define TOTC (NMT * NCHUNK)     // 256

#define PKF 512                 // packed floats per row (hi/lo interleaved)

#define RSB 320                 // smem row stride bytes (20 x 16B units, conflict-free)
#define ATILEB (BN * RSB)       // 20480
#define BTILEB (BMT * RSB)      // 20480
#define BUFB   (ATILEB + BTILEB)
#define RED_OFF (2 * BUFB)      // 81920
#define SMEM_TOTAL (2 * BUFB + 4 * 64 * 8)   // 83968 B -> 2 CTAs/SM

__device__ float g_ixn[BB * NN];
__device__ float g_iyn[BB * MM];
__device__ float g_psrc[BB * NN * PKF];
__device__ float g_pdst[BB * MM * PKF];

static __device__ __forceinline__ uint32_t smem_u32(const void* p) {
    uint32_t a;
    asm("{ .reg .u64 t; cvta.to.shared.u64 t, %1; cvt.u32.u64 %0, t; }" : "=r"(a) : "l"(p));
    return a;
}
static __device__ __forceinline__ void cpasync16(uint32_t saddr, const void* g) {
    asm volatile("cp.async.cg.shared.global [%0], [%1], 16;" :: "r"(saddr), "l"(g));
}
static __device__ __forceinline__ void cp_commit() {
    asm volatile("cp.async.commit_group;" ::: "memory");
}
template <int N>
static __device__ __forceinline__ void cp_wait() {
    asm volatile("cp.async.wait_group %0;" :: "n"(N) : "memory");
}
static __device__ __forceinline__ void split1(float x, float& h, float& l) {
    uint32_t hh;
    asm("cvt.rna.tf32.f32 %0, %1;" : "=r"(hh) : "f"(x));
    h = __uint_as_float(hh);
    float r = x - h;
    uint32_t ll;
    asm("cvt.rna.tf32.f32 %0, %1;" : "=r"(ll) : "f"(r));
    l = __uint_as_float(ll);
}
static __device__ __forceinline__ void mma8(float* d, const uint32_t* a, const uint32_t* b) {
    asm volatile(
        "mma.sync.aligned.m16n8k8.row.col.f32.tf32.tf32.f32 "
        "{%0,%1,%2,%3}, {%4,%5,%6,%7}, {%8,%9}, {%0,%1,%2,%3};"
        : "+f"(d[0]), "+f"(d[1]), "+f"(d[2]), "+f"(d[3])
        : "r"(a[0]), "r"(a[1]), "r"(a[2]), "r"(a[3]), "r"(b[0]), "r"(b[1]));
}

// Prepass: inverse L2 norm + packed hi/lo tf32 in MMA fragment order.
__global__ __launch_bounds__(TPB)
void pack_kernel(const float* __restrict__ src, const float* __restrict__ dst) {
    __shared__ float stage[8][264];
    const int wid = threadIdx.x >> 5, lane = threadIdx.x & 31;
    int row = blockIdx.x * 8 + wid;
    const float* p;
    float* onorm;
    float* pk;
    int r;
    if (row < BB * NN) { p = src; onorm = g_ixn; pk = g_psrc; r = row; }
    else               { p = dst; onorm = g_iyn; pk = g_pdst; r = row - BB * NN; }

    const float4* v = (const float4*)(p + (size_t)r * DD);
    float4 x0 = v[lane * 2], x1 = v[lane * 2 + 1];
    *(float4*)&stage[wid][lane * 8]     = x0;
    *(float4*)&stage[wid][lane * 8 + 4] = x1;
    float s = x0.x * x0.x + x0.y * x0.y + x0.z * x0.z + x0.w * x0.w
            + x1.x * x1.x + x1.y * x1.y + x1.z * x1.z + x1.w * x1.w;
    #pragma unroll
    for (int off = 16; off; off >>= 1) s += __shfl_xor_sync(0xffffffffu, s, off);
    if (lane == 0) onorm[r] = 1.0f / sqrtf(s);
    __syncwarp();

    float4* outp = (float4*)(pk + (size_t)r * PKF);
    #pragma unroll
    for (int i = 0; i < 4; i++) {
        int u = lane + 32 * i;
        int c = u >> 4, q = u & 15;
        int ks = q >> 2, g = q & 3;
        int k = c * 32 + ks * 8 + g;
        float h0, l0, h1, l1;
        split1(stage[wid][k],     h0, l0);
        split1(stage[wid][k + 4], h1, l1);
        outp[u] = make_float4(h0, h1, l0, l1);
    }
}

__global__ __launch_bounds__(TPB, 2)
void match_kernel(const float* __restrict__ pts, float* __restrict__ out) {
    extern __shared__ char sm[];
    const uint32_t sb = smem_u32(sm);
    const int tid  = threadIdx.x;
    const int lane = tid & 31;
    const int wid  = tid >> 5;
    const int gid  = lane >> 2;
    const int tig  = lane & 3;
    const int wr   = wid & 1;      // row band: rows wr*32..+31
    const int wc   = wid >> 1;     // col band: cols wc*16..+15
    const int b  = blockIdx.y;
    const int n0 = blockIdx.x * BN;

    const float* gAp = g_psrc + ((size_t)b * NN + n0) * PKF;
    const float* gBp = g_pdst + (size_t)b * MM * PKF;

    auto issue = [&](int cc, int q) {
        const float* gB = gBp + (size_t)(cc >> 3) * BMT * PKF;
        const int ch = cc & 7;
        const uint32_t aBase = sb + q * BUFB;
        const uint32_t bBase = aBase + ATILEB;
        #pragma unroll
        for (int i = 0; i < 4; i++) {       // A: 64 rows x 16 units
            int lin = tid + i * TPB;
            int row = lin >> 4, u = lin & 15;
            cpasync16(aBase + row * RSB + u * 16,
                      gAp + (size_t)row * PKF + ch * 64 + u * 4);
        }
        #pragma unroll
        for (int i = 0; i < 4; i++) {       // B: 64 rows x 16 units
            int lin = tid + i * TPB;
            int row = lin >> 4, u = lin & 15;
            cpasync16(bBase + row * RSB + u * 16,
                      gB + (size_t)row * PKF + ch * 64 + u * 4);
        }
        cp_commit();
    };

    float acc[2][2][4];
    #pragma unroll
    for (int i = 0; i < 2; i++)
        #pragma unroll
        for (int j = 0; j < 2; j++)
            #pragma unroll
            for (int k = 0; k < 4; k++) acc[i][j][k] = 0.0f;

    float best[4];
    int   bidx[4];
    #pragma unroll
    for (int j = 0; j < 4; j++) { best[j] = -1e30f; bidx[j] = 0; }

    issue(0, 0);

    #pragma unroll 1
    for (int cc = 0; cc < TOTC; cc++) {
        const int q = cc & 1;
        if (cc + 1 < TOTC) { issue(cc + 1, q ^ 1); cp_wait<1>(); }
        else               { cp_wait<0>(); }
        __syncthreads();

        const char* A  = sm + q * BUFB;
        const char* Bm = A + ATILEB;

        #pragma unroll
        for (int ks = 0; ks < 4; ks++) {
            const int uoff = (ks * 4 + tig) * 16;
            uint32_t aH[2][4], aL[2][4];
            #pragma unroll
            for (int mt2 = 0; mt2 < 2; mt2++) {
                int r0 = wr * 32 + mt2 * 16 + gid;
                float4 v0 = *(const float4*)(A + r0 * RSB + uoff);
                float4 v1 = *(const float4*)(A + (r0 + 8) * RSB + uoff);
                aH[mt2][0] = __float_as_uint(v0.x);
                aH[mt2][1] = __float_as_uint(v1.x);
                aH[mt2][2] = __float_as_uint(v0.y);
                aH[mt2][3] = __float_as_uint(v1.y);
                aL[mt2][0] = __float_as_uint(v0.z);
                aL[mt2][1] = __float_as_uint(v1.z);
                aL[mt2][2] = __float_as_uint(v0.w);
                aL[mt2][3] = __float_as_uint(v1.w);
            }
            uint32_t bH[2][2], bL[2][2];
            #pragma unroll
            for (int nt = 0; nt < 2; nt++) {
                int rn = wc * 16 + nt * 8 + gid;
                float4 v = *(const float4*)(Bm + rn * RSB + uoff);
                bH[nt][0] = __float_as_uint(v.x);
                bH[nt][1] = __float_as_uint(v.y);
                bL[nt][0] = __float_as_uint(v.z);
                bL[nt][1] = __float_as_uint(v.w);
            }
            #pragma unroll
            for (int mt2 = 0; mt2 < 2; mt2++)
                #pragma unroll
                for (int nt = 0; nt < 2; nt++) {
                    mma8(acc[mt2][nt], aH[mt2], bH[nt]);   // hh
                    mma8(acc[mt2][nt], aH[mt2], bL[nt]);   // hl
                    mma8(acc[mt2][nt], aL[mt2], bH[nt]);   // lh
                }
        }

        if ((cc & 7) == 7) {
            const int mt = cc >> 3;
            const int mbase = mt * BMT + wc * 16;
            const float* iy = g_iyn + b * MM + mbase;
            #pragma unroll
            for (int nt = 0; nt < 2; nt++) {
                float2 y2 = *(const float2*)(iy + nt * 8 + 2 * tig);
                int m0 = mbase + nt * 8 + 2 * tig;
                #pragma unroll
                for (int mt2 = 0; mt2 < 2; mt2++) {
                    float v0 = acc[mt2][nt][0] * y2.x;
                    float v1 = acc[mt2][nt][1] * y2.y;
                    float v2 = acc[mt2][nt][2] * y2.x;
                    float v3 = acc[mt2][nt][3] * y2.y;
                    int j0 = mt2 * 2, j1 = mt2 * 2 + 1;
                    if (v0 > best[j0]) { best[j0] = v0; bidx[j0] = m0; }
                    if (v1 > best[j0]) { best[j0] = v1; bidx[j0] = m0 + 1; }
                    if (v2 > best[j1]) { best[j1] = v2; bidx[j1] = m0; }
                    if (v3 > best[j1]) { best[j1] = v3; bidx[j1] = m0 + 1; }
                    acc[mt2][nt][0] = 0.0f; acc[mt2][nt][1] = 0.0f;
                    acc[mt2][nt][2] = 0.0f; acc[mt2][nt][3] = 0.0f;
                }
            }
        }
        __syncthreads();
    }

    // reduce across quad lanes (cols), stash per col-band, final merge of 4 bands
    float* sval = (float*)(sm + RED_OFF);
    int*   sidx = (int*)(sm + RED_OFF + 4 * 64 * 4);
    #pragma unroll
    for (int j = 0; j < 4; j++) {
        float v = best[j];
        int   id = bidx[j];
        #pragma unroll
        for (int off = 1; off < 4; off <<= 1) {
            float ov = __shfl_xor_sync(0xffffffffu, v, off);
            int   oi = __shfl_xor_sync(0xffffffffu, id, off);
            if (ov > v || (ov == v && oi < id)) { v = ov; id = oi; }
        }
        if (tig == 0) {
            int r = wr * 32 + (j >> 1) * 16 + (j & 1) * 8 + gid;   // 0..63
            sval[wc * 64 + r] = v;
            sidx[wc * 64 + r] = id;
        }
    }
    __syncthreads();

    if (tid < 64) {
        int r = tid;
        float v = sval[r];
        int id = sidx[r];
        #pragma unroll
        for (int wcb = 1; wcb < 4; wcb++) {
            float ov = sval[wcb * 64 + r];
            int   oi = sidx[wcb * 64 + r];
            if (ov > v || (ov == v && oi < id)) { v = ov; id = oi; }
        }
        int n = n0 + r;
        float conf = v * g_ixn[b * NN + n];
        size_t ob = (size_t)b * NN + n;
        out[ob * 2]     = pts[((size_t)b * MM + id) * 2];
        out[ob * 2 + 1] = pts[((size_t)b * MM + id) * 2 + 1];
        out[(size_t)BB * NN * 2 + ob] = conf;
    }
}

extern "C" void kernel_launch(void* const* d_in, const int* in_sizes, int n_in,
                              void* d_out, int out_size) {
    const float* desc_src = (const float*)d_in[0];
    const float* desc_dst = (const float*)d_in[1];
    const float* points_dst = (const float*)d_in[2];
    float* out = (float*)d_out;

    cudaFuncSetAttribute(match_kernel, cudaFuncAttributeMaxDynamicSharedMemorySize,
                         SMEM_TOTAL);

    pack_kernel<<<(2 * BB * NN) / 8, TPB>>>(desc_src, desc_dst);

    dim3 grid(NN / BN, BB);   // 32 x 8 = 256 CTAs
    match_kernel<<<grid, TPB, SMEM_TOTAL>>>(points_dst, out);
}

// round 7
// speedup vs baseline: 1.1050x; 1.1050x over previous
#include <cuda_runtime.h>
#include <cstdint>
#include <math.h>

#define BB 8
#define NN 2048
#define MM 2048
#define DD 256

#define TPB 256
#define BN  128                 // src rows per CTA (MMA M)
#define BMT 128                 // dst rows per m-tile
#define KC  32                  // k per chunk
#define NMT (MM / BMT)          // 16
#define NCHUNK (DD / KC)        // 8
#define TOTC (NMT * NCHUNK)     // 128 chunks

#define PKF 512                 // packed floats per row: 256 k * (hi+lo)

// 256B rows, XOR-swizzled 16B units: unit su = u ^ (row & 7)
#define SWU(row, u) (((row) << 8) + ((((u) ^ ((row) & 7))) << 4))
#define ATILEB (128 * 256)              // 32768 B per tile
#define BUFB   (2 * ATILEB)             // A + B per stage = 65536 B
#define NSTAGE 3
#define RED_OFF (NSTAGE * BUFB)         // 196608
#define SMEM_TOTAL (NSTAGE * BUFB + 2048)   // 198656 B -> 1 CTA/SM

__device__ float g_ixn[BB * NN];
__device__ float g_iyn[BB * MM];
__device__ float g_psrc[BB * NN * PKF];   // packed hi/lo tf32
__device__ float g_pdst[BB * MM * PKF];

static __device__ __forceinline__ uint32_t smem_u32(const void* p) {
    uint32_t a;
    asm("{ .reg .u64 t; cvta.to.shared.u64 t, %1; cvt.u32.u64 %0, t; }" : "=r"(a) : "l"(p));
    return a;
}
static __device__ __forceinline__ void cpasync16(uint32_t saddr, const void* g) {
    asm volatile("cp.async.cg.shared.global [%0], [%1], 16;" :: "r"(saddr), "l"(g));
}
static __device__ __forceinline__ void cp_commit() {
    asm volatile("cp.async.commit_group;" ::: "memory");
}
template <int N>
static __device__ __forceinline__ void cp_wait() {
    asm volatile("cp.async.wait_group %0;" :: "n"(N) : "memory");
}
static __device__ __forceinline__ void split1(float x, float& h, float& l) {
    uint32_t hh;
    asm("cvt.rna.tf32.f32 %0, %1;" : "=r"(hh) : "f"(x));
    h = __uint_as_float(hh);
    float r = x - h;
    uint32_t ll;
    asm("cvt.rna.tf32.f32 %0, %1;" : "=r"(ll) : "f"(r));
    l = __uint_as_float(ll);
}
static __device__ __forceinline__ void mma8(float* d, const uint32_t* a, const uint32_t* b) {
    asm volatile(
        "mma.sync.aligned.m16n8k8.row.col.f32.tf32.tf32.f32 "
        "{%0,%1,%2,%3}, {%4,%5,%6,%7}, {%8,%9}, {%0,%1,%2,%3};"
        : "+f"(d[0]), "+f"(d[1]), "+f"(d[2]), "+f"(d[3])
        : "r"(a[0]), "r"(a[1]), "r"(a[2]), "r"(a[3]), "r"(b[0]), "r"(b[1]));
}

// Prepass: inverse L2 norm + packed hi/lo tf32 in MMA fragment order.
// unit u (16B) of chunk c = {hi_k, hi_{k+4}, lo_k, lo_{k+4}}, k = c*32 + (u%16/4)*8 + u%4
__global__ __launch_bounds__(TPB)
void pack_kernel(const float* __restrict__ src, const float* __restrict__ dst) {
    __shared__ float stage[8][264];
    const int wid = threadIdx.x >> 5, lane = threadIdx.x & 31;
    int row = blockIdx.x * 8 + wid;
    const float* p;
    float* onorm;
    float* pk;
    int r;
    if (row < BB * NN) { p = src; onorm = g_ixn; pk = g_psrc; r = row; }
    else               { p = dst; onorm = g_iyn; pk = g_pdst; r = row - BB * NN; }

    const float4* v = (const float4*)(p + (size_t)r * DD);
    float4 x0 = v[lane * 2], x1 = v[lane * 2 + 1];
    *(float4*)&stage[wid][lane * 8]     = x0;
    *(float4*)&stage[wid][lane * 8 + 4] = x1;
    float s = x0.x * x0.x + x0.y * x0.y + x0.z * x0.z + x0.w * x0.w
            + x1.x * x1.x + x1.y * x1.y + x1.z * x1.z + x1.w * x1.w;
    #pragma unroll
    for (int off = 16; off; off >>= 1) s += __shfl_xor_sync(0xffffffffu, s, off);
    if (lane == 0) onorm[r] = 1.0f / sqrtf(s);
    __syncwarp();

    float4* outp = (float4*)(pk + (size_t)r * PKF);
    #pragma unroll
    for (int i = 0; i < 4; i++) {
        int u = lane + 32 * i;
        int c = u >> 4, q = u & 15;
        int ks = q >> 2, g = q & 3;
        int k = c * 32 + ks * 8 + g;
        float h0, l0, h1, l1;
        split1(stage[wid][k],     h0, l0);
        split1(stage[wid][k + 4], h1, l1);
        outp[u] = make_float4(h0, h1, l0, l1);
    }
}

__global__ __launch_bounds__(TPB, 1)
void match_kernel(const float* __restrict__ pts, float* __restrict__ out) {
    extern __shared__ char sm[];
    const uint32_t sb = smem_u32(sm);
    const int tid = threadIdx.x;
    const int lane = tid & 31;
    const int wid  = tid >> 5;
    const int gid  = lane >> 2;
    const int tig  = lane & 3;
    const int wr   = wid & 3;    // row band: rows wr*32..+31
    const int wcc  = wid >> 2;   // col band (0/1): cols wcc*64..+63
    const int b  = blockIdx.y;
    const int n0 = blockIdx.x * BN;

    const float* gAp = g_psrc + ((size_t)b * NN + n0) * PKF;
    const float* gBp = g_pdst + (size_t)b * MM * PKF;

    // Issue cp.async for chunk cc into stage st (body only; caller commits).
    auto issue = [&](int cc, int st) {
        const float* gB = gBp + (size_t)(cc >> 3) * BMT * PKF;
        const int ch = cc & 7;
        const uint32_t aBase = sb + st * BUFB;
        const uint32_t bBase = aBase + ATILEB;
        #pragma unroll
        for (int i = 0; i < 8; i++) {          // A: 128 rows x 16 units
            int lin = tid + i * TPB;
            int row = lin >> 4, u = lin & 15;
            cpasync16(aBase + SWU(row, u), gAp + (size_t)row * PKF + ch * 64 + u * 4);
        }
        #pragma unroll
        for (int i = 0; i < 8; i++) {          // B: 128 rows x 16 units
            int lin = tid + i * TPB;
            int row = lin >> 4, u = lin & 15;
            cpasync16(bBase + SWU(row, u), gB + (size_t)row * PKF + ch * 64 + u * 4);
        }
    };

    float acc[2][8][4];
    #pragma unroll
    for (int i = 0; i < 2; i++)
        #pragma unroll
        for (int j = 0; j < 8; j++)
            #pragma unroll
            for (int k = 0; k < 4; k++) acc[i][j][k] = 0.0f;

    float best[4];
    int   bidx[4];
    #pragma unroll
    for (int j = 0; j < 4; j++) { best[j] = -1e30f; bidx[j] = 0; }

    issue(0, 0); cp_commit();
    issue(1, 1); cp_commit();

    int st = 0;                    // stage of current chunk
    #pragma unroll 1
    for (int cc = 0; cc < TOTC; cc++) {
        cp_wait<1>();              // chunk cc resident (this thread's copies)
        __syncthreads();           // publish all threads' copies; proves cc-1 reads done

        {                          // prefetch chunk cc+2 into the stage freed by cc-1
            int st2 = st + 2; if (st2 >= NSTAGE) st2 -= NSTAGE;
            if (cc + 2 < TOTC) issue(cc + 2, st2);
            cp_commit();           // commit every iteration to keep group indexing uniform
        }

        const char* A  = sm + st * BUFB;
        const char* Bm = A + ATILEB;

        #pragma unroll
        for (int ks = 0; ks < 4; ks++) {
            const int u = ks * 4 + tig;
            uint32_t aH[2][4], aL[2][4];
            #pragma unroll
            for (int mt2 = 0; mt2 < 2; mt2++) {
                int r0 = wr * 32 + mt2 * 16 + gid;
                float4 v0 = *(const float4*)(A + SWU(r0, u));
                float4 v1 = *(const float4*)(A + SWU(r0 + 8, u));
                aH[mt2][0] = __float_as_uint(v0.x);
                aH[mt2][1] = __float_as_uint(v1.x);
                aH[mt2][2] = __float_as_uint(v0.y);
                aH[mt2][3] = __float_as_uint(v1.y);
                aL[mt2][0] = __float_as_uint(v0.z);
                aL[mt2][1] = __float_as_uint(v1.z);
                aL[mt2][2] = __float_as_uint(v0.w);
                aL[mt2][3] = __float_as_uint(v1.w);
            }
            uint32_t bH[8][2], bL[8][2];
            #pragma unroll
            for (int nt = 0; nt < 8; nt++) {
                int rn = wcc * 64 + nt * 8 + gid;
                float4 v = *(const float4*)(Bm + SWU(rn, u));
                bH[nt][0] = __float_as_uint(v.x);
                bH[nt][1] = __float_as_uint(v.y);
                bL[nt][0] = __float_as_uint(v.z);
                bL[nt][1] = __float_as_uint(v.w);
            }
            #pragma unroll
            for (int mt2 = 0; mt2 < 2; mt2++)
                #pragma unroll
                for (int nt = 0; nt < 8; nt++) {
                    mma8(acc[mt2][nt], aH[mt2], bH[nt]);   // hh
                    mma8(acc[mt2][nt], aH[mt2], bL[nt]);   // hl
                    mma8(acc[mt2][nt], aL[mt2], bH[nt]);   // lh
                }
        }

        if ((cc & 7) == 7) {
            const int mt = cc >> 3;
            const int mbase = mt * BMT + wcc * 64;
            const float* iy = g_iyn + b * MM + mbase;
            #pragma unroll
            for (int nt = 0; nt < 8; nt++) {
                float2 y2 = *(const float2*)(iy + nt * 8 + 2 * tig);
                int m0 = mbase + nt * 8 + 2 * tig;
                #pragma unroll
                for (int mt2 = 0; mt2 < 2; mt2++) {
                    float v0 = acc[mt2][nt][0] * y2.x;
                    float v1 = acc[mt2][nt][1] * y2.y;
                    float v2 = acc[mt2][nt][2] * y2.x;
                    float v3 = acc[mt2][nt][3] * y2.y;
                    int j0 = mt2 * 2, j1 = mt2 * 2 + 1;
                    if (v0 > best[j0]) { best[j0] = v0; bidx[j0] = m0; }
                    if (v1 > best[j0]) { best[j0] = v1; bidx[j0] = m0 + 1; }
                    if (v2 > best[j1]) { best[j1] = v2; bidx[j1] = m0; }
                    if (v3 > best[j1]) { best[j1] = v3; bidx[j1] = m0 + 1; }
                    acc[mt2][nt][0] = 0.0f; acc[mt2][nt][1] = 0.0f;
                    acc[mt2][nt][2] = 0.0f; acc[mt2][nt][3] = 0.0f;
                }
            }
        }

        if (++st == NSTAGE) st = 0;
    }
    __syncthreads();   // protect reduction scratch (reuses smem region semantics)

    // reduce across quad lanes, stash per col-band, merge 2 bands
    float* sval = (float*)(sm + RED_OFF);
    int*   sidx = (int*)(sm + RED_OFF + 2 * 128 * 4);
    #pragma unroll
    for (int j = 0; j < 4; j++) {
        float v = best[j];
        int   id = bidx[j];
        #pragma unroll
        for (int off = 1; off < 4; off <<= 1) {
            float ov = __shfl_xor_sync(0xffffffffu, v, off);
            int   oi = __shfl_xor_sync(0xffffffffu, id, off);
            if (ov > v || (ov == v && oi < id)) { v = ov; id = oi; }
        }
        if (tig == 0) {
            int r = wr * 32 + (j >> 1) * 16 + (j & 1) * 8 + gid;   // 0..127
            sval[wcc * 128 + r] = v;
            sidx[wcc * 128 + r] = id;
        }
    }
    __syncthreads();

    if (tid < 128) {
        int r = tid;
        float v0 = sval[r], v1 = sval[128 + r];
        int i0 = sidx[r], i1 = sidx[128 + r];
        float v = v0;
        int id = i0;
        if (v1 > v0 || (v1 == v0 && i1 < i0)) { v = v1; id = i1; }
        int n = n0 + r;
        float conf = v * g_ixn[b * NN + n];
        size_t ob = (size_t)b * NN + n;
        out[ob * 2]     = pts[((size_t)b * MM + id) * 2];
        out[ob * 2 + 1] = pts[((size_t)b * MM + id) * 2 + 1];
        out[(size_t)BB * NN * 2 + ob] = conf;
    }
}

extern "C" void kernel_launch(void* const* d_in, const int* in_sizes, int n_in,
                              void* d_out, int out_size) {
    const float* desc_src = (const float*)d_in[0];
    const float* desc_dst = (const float*)d_in[1];
    const float* points_dst = (const float*)d_in[2];
    float* out = (float*)d_out;

    cudaFuncSetAttribute(match_kernel, cudaFuncAttributeMaxDynamicSharedMemorySize,
                         SMEM_TOTAL);

    pack_kernel<<<(2 * BB * NN) / 8, TPB>>>(desc_src, desc_dst);

    dim3 grid(NN / BN, BB);   // 16 x 8 = 128 CTAs
    match_kernel<<<grid, TPB, SMEM_TOTAL>>>(points_dst, out);
}

// round 10
// speedup vs baseline: 1.2394x; 1.1216x over previous
#include <cuda_runtime.h>
#include <cstdint>
#include <math.h>

#define BB 8
#define NN 2048
#define MM 2048
#define DD 256

#define TPB 256
#define BN  128                 // src rows per CTA (MMA M)
#define BMT 128                 // dst rows per m-tile
#define KC  32                  // k per chunk
#define NMT (MM / BMT)          // 16
#define NCHUNK (DD / KC)        // 8
#define TOTC (NMT * NCHUNK)     // 128 chunks

#define PKF 512                 // packed floats per row: 256 k * (hi+lo)

// 256B rows; 16B units XOR-swizzled: su = u ^ ((row&1)<<2)
// STS phase (same row, u 0..7): distinct banks. LDS.128 phase (rows {2p,2p+1},
// u in {c..c+3}): even row -> {c..c+3}, odd row -> complementary half. Conflict-free.
#define SWU(row, u) (((row) << 8) + ((((u) ^ (((row) & 1) << 2))) << 4))
#define ATILEB (128 * 256)              // 32768 B per tile
#define BUFB   (2 * ATILEB)             // A + B per stage = 65536 B
#define NSTAGE 3
#define RED_OFF (NSTAGE * BUFB)         // 196608
#define SMEM_TOTAL (NSTAGE * BUFB + 2048)   // 198656 B -> 1 CTA/SM

__device__ float g_ixn[BB * NN];
__device__ float g_iyn[BB * MM];
__device__ float g_psrc[BB * NN * PKF];   // packed hi/lo tf32
__device__ float g_pdst[BB * MM * PKF];

static __device__ __forceinline__ uint32_t smem_u32(const void* p) {
    uint32_t a;
    asm("{ .reg .u64 t; cvta.to.shared.u64 t, %1; cvt.u32.u64 %0, t; }" : "=r"(a) : "l"(p));
    return a;
}
static __device__ __forceinline__ void cpasync16(uint32_t saddr, const void* g) {
    asm volatile("cp.async.cg.shared.global [%0], [%1], 16;" :: "r"(saddr), "l"(g));
}
static __device__ __forceinline__ void cp_commit() {
    asm volatile("cp.async.commit_group;" ::: "memory");
}
template <int N>
static __device__ __forceinline__ void cp_wait() {
    asm volatile("cp.async.wait_group %0;" :: "n"(N) : "memory");
}
static __device__ __forceinline__ void split1(float x, float& h, float& l) {
    uint32_t hh;
    asm("cvt.rna.tf32.f32 %0, %1;" : "=r"(hh) : "f"(x));
    h = __uint_as_float(hh);
    float r = x - h;
    uint32_t ll;
    asm("cvt.rna.tf32.f32 %0, %1;" : "=r"(ll) : "f"(r));
    l = __uint_as_float(ll);
}
static __device__ __forceinline__ void mma8(float* d, const uint32_t* a, const uint32_t* b) {
    asm volatile(
        "mma.sync.aligned.m16n8k8.row.col.f32.tf32.tf32.f32 "
        "{%0,%1,%2,%3}, {%4,%5,%6,%7}, {%8,%9}, {%0,%1,%2,%3};"
        : "+f"(d[0]), "+f"(d[1]), "+f"(d[2]), "+f"(d[3])
        : "r"(a[0]), "r"(a[1]), "r"(a[2]), "r"(a[3]), "r"(b[0]), "r"(b[1]));
}

// Prepass: inverse L2 norm + packed hi/lo tf32 in MMA fragment order.
__global__ __launch_bounds__(TPB)
void pack_kernel(const float* __restrict__ src, const float* __restrict__ dst) {
    __shared__ float stage[8][264];
    const int wid = threadIdx.x >> 5, lane = threadIdx.x & 31;
    int row = blockIdx.x * 8 + wid;
    const float* p;
    float* onorm;
    float* pk;
    int r;
    if (row < BB * NN) { p = src; onorm = g_ixn; pk = g_psrc; r = row; }
    else               { p = dst; onorm = g_iyn; pk = g_pdst; r = row - BB * NN; }

    const float4* v = (const float4*)(p + (size_t)r * DD);
    float4 x0 = v[lane * 2], x1 = v[lane * 2 + 1];
    *(float4*)&stage[wid][lane * 8]     = x0;
    *(float4*)&stage[wid][lane * 8 + 4] = x1;
    float s = x0.x * x0.x + x0.y * x0.y + x0.z * x0.z + x0.w * x0.w
            + x1.x * x1.x + x1.y * x1.y + x1.z * x1.z + x1.w * x1.w;
    #pragma unroll
    for (int off = 16; off; off >>= 1) s += __shfl_xor_sync(0xffffffffu, s, off);
    if (lane == 0) onorm[r] = 1.0f / sqrtf(s);
    __syncwarp();

    float4* outp = (float4*)(pk + (size_t)r * PKF);
    #pragma unroll
    for (int i = 0; i < 4; i++) {
        int u = lane + 32 * i;
        int c = u >> 4, q = u & 15;
        int ks = q >> 2, g = q & 3;
        int k = c * 32 + ks * 8 + g;
        float h0, l0, h1, l1;
        split1(stage[wid][k],     h0, l0);
        split1(stage[wid][k + 4], h1, l1);
        outp[u] = make_float4(h0, h1, l0, l1);
    }
}

__global__ __launch_bounds__(TPB, 1)
void match_kernel(const float* __restrict__ pts, float* __restrict__ out) {
    extern __shared__ char sm[];
    const uint32_t sb = smem_u32(sm);
    const int tid = threadIdx.x;
    const int lane = tid & 31;
    const int wid  = tid >> 5;
    const int gid  = lane >> 2;
    const int tig  = lane & 3;
    const int wr   = wid & 3;    // row band: rows wr*32..+31
    const int wcc  = wid >> 2;   // col band (0/1): cols wcc*64..+63
    const int b  = blockIdx.y;
    const int n0 = blockIdx.x * BN;

    const float* gAp = g_psrc + ((size_t)b * NN + n0) * PKF;
    const float* gBp = g_pdst + (size_t)b * MM * PKF;

    auto issue = [&](int cc, int st) {
        const float* gB = gBp + (size_t)(cc >> 3) * BMT * PKF;
        const int ch = cc & 7;
        const uint32_t aBase = sb + st * BUFB;
        const uint32_t bBase = aBase + ATILEB;
        #pragma unroll
        for (int i = 0; i < 8; i++) {          // A: 128 rows x 16 units
            int lin = tid + i * TPB;
            int row = lin >> 4, u = lin & 15;
            cpasync16(aBase + SWU(row, u), gAp + (size_t)row * PKF + ch * 64 + u * 4);
        }
        #pragma unroll
        for (int i = 0; i < 8; i++) {          // B: 128 rows x 16 units
            int lin = tid + i * TPB;
            int row = lin >> 4, u = lin & 15;
            cpasync16(bBase + SWU(row, u), gB + (size_t)row * PKF + ch * 64 + u * 4);
        }
    };

    float acc[2][8][4];
    #pragma unroll
    for (int i = 0; i < 2; i++)
        #pragma unroll
        for (int j = 0; j < 8; j++)
            #pragma unroll
            for (int k = 0; k < 4; k++) acc[i][j][k] = 0.0f;

    float best[4];
    int   bidx[4];
    #pragma unroll
    for (int j = 0; j < 4; j++) { best[j] = -1e30f; bidx[j] = 0; }

    issue(0, 0); cp_commit();
    issue(1, 1); cp_commit();

    int st = 0;
    #pragma unroll 1
    for (int cc = 0; cc < TOTC; cc++) {
        cp_wait<1>();              // chunk cc resident (this thread's copies)
        __syncthreads();           // publish; also proves cc-1 reads finished

        {                          // prefetch cc+2 into stage freed by cc-1
            int st2 = st + 2; if (st2 >= NSTAGE) st2 -= NSTAGE;
            if (cc + 2 < TOTC) issue(cc + 2, st2);
            cp_commit();           // uniform group indexing
        }

        const char* A  = sm + st * BUFB;
        const char* Bm = A + ATILEB;

        #pragma unroll
        for (int ks = 0; ks < 4; ks++) {
            const int u = ks * 4 + tig;
            uint32_t aH[2][4], aL[2][4];
            #pragma unroll
            for (int mt2 = 0; mt2 < 2; mt2++) {
                int r0 = wr * 32 + mt2 * 16 + gid;
                float4 v0 = *(const float4*)(A + SWU(r0, u));
                float4 v1 = *(const float4*)(A + SWU(r0 + 8, u));
                aH[mt2][0] = __float_as_uint(v0.x);
                aH[mt2][1] = __float_as_uint(v1.x);
                aH[mt2][2] = __float_as_uint(v0.y);
                aH[mt2][3] = __float_as_uint(v1.y);
                aL[mt2][0] = __float_as_uint(v0.z);
                aL[mt2][1] = __float_as_uint(v1.z);
                aL[mt2][2] = __float_as_uint(v0.w);
                aL[mt2][3] = __float_as_uint(v1.w);
            }
            uint32_t bH[8][2], bL[8][2];
            #pragma unroll
            for (int nt = 0; nt < 8; nt++) {
                int rn = wcc * 64 + nt * 8 + gid;
                float4 v = *(const float4*)(Bm + SWU(rn, u));
                bH[nt][0] = __float_as_uint(v.x);
                bH[nt][1] = __float_as_uint(v.y);
                bL[nt][0] = __float_as_uint(v.z);
                bL[nt][1] = __float_as_uint(v.w);
            }
            #pragma unroll
            for (int mt2 = 0; mt2 < 2; mt2++)
                #pragma unroll
                for (int nt = 0; nt < 8; nt++) {
                    mma8(acc[mt2][nt], aH[mt2], bH[nt]);   // hh
                    mma8(acc[mt2][nt], aH[mt2], bL[nt]);   // hl
                    mma8(acc[mt2][nt], aL[mt2], bH[nt]);   // lh
                }
        }

        if ((cc & 7) == 7) {
            const int mt = cc >> 3;
            const int mbase = mt * BMT + wcc * 64;
            const float* iy = g_iyn + b * MM + mbase;
            #pragma unroll
            for (int nt = 0; nt < 8; nt++) {
                float2 y2 = *(const float2*)(iy + nt * 8 + 2 * tig);
                int m0 = mbase + nt * 8 + 2 * tig;
                #pragma unroll
                for (int mt2 = 0; mt2 < 2; mt2++) {
                    float v0 = acc[mt2][nt][0] * y2.x;
                    float v1 = acc[mt2][nt][1] * y2.y;
                    float v2 = acc[mt2][nt][2] * y2.x;
                    float v3 = acc[mt2][nt][3] * y2.y;
                    int j0 = mt2 * 2, j1 = mt2 * 2 + 1;
                    if (v0 > best[j0]) { best[j0] = v0; bidx[j0] = m0; }
                    if (v1 > best[j0]) { best[j0] = v1; bidx[j0] = m0 + 1; }
                    if (v2 > best[j1]) { best[j1] = v2; bidx[j1] = m0; }
                    if (v3 > best[j1]) { best[j1] = v3; bidx[j1] = m0 + 1; }
                    acc[mt2][nt][0] = 0.0f; acc[mt2][nt][1] = 0.0f;
                    acc[mt2][nt][2] = 0.0f; acc[mt2][nt][3] = 0.0f;
                }
            }
        }

        if (++st == NSTAGE) st = 0;
    }
    __syncthreads();

    // reduce across quad lanes, stash per col-band, merge 2 bands
    float* sval = (float*)(sm + RED_OFF);
    int*   sidx = (int*)(sm + RED_OFF + 2 * 128 * 4);
    #pragma unroll
    for (int j = 0; j < 4; j++) {
        float v = best[j];
        int   id = bidx[j];
        #pragma unroll
        for (int off = 1; off < 4; off <<= 1) {
            float ov = __shfl_xor_sync(0xffffffffu, v, off);
            int   oi = __shfl_xor_sync(0xffffffffu, id, off);
            if (ov > v || (ov == v && oi < id)) { v = ov; id = oi; }
        }
        if (tig == 0) {
            int r = wr * 32 + (j >> 1) * 16 + (j & 1) * 8 + gid;   // 0..127
            sval[wcc * 128 + r] = v;
            sidx[wcc * 128 + r] = id;
        }
    }
    __syncthreads();

    if (tid < 128) {
        int r = tid;
        float v0 = sval[r], v1 = sval[128 + r];
        int i0 = sidx[r], i1 = sidx[128 + r];
        float v = v0;
        int id = i0;
        if (v1 > v0 || (v1 == v0 && i1 < i0)) { v = v1; id = i1; }
        int n = n0 + r;
        float conf = v * g_ixn[b * NN + n];
        size_t ob = (size_t)b * NN + n;
        out[ob * 2]     = pts[((size_t)b * MM + id) * 2];
        out[ob * 2 + 1] = pts[((size_t)b * MM + id) * 2 + 1];
        out[(size_t)BB * NN * 2 + ob] = conf;
    }
}

extern "C" void kernel_launch(void* const* d_in, const int* in_sizes, int n_in,
                              void* d_out, int out_size) {
    const float* desc_src = (const float*)d_in[0];
    const float* desc_dst = (const float*)d_in[1];
    const float* points_dst = (const float*)d_in[2];
    float* out = (float*)d_out;

    cudaFuncSetAttribute(match_kernel, cudaFuncAttributeMaxDynamicSharedMemorySize,
                         SMEM_TOTAL);

    pack_kernel<<<(2 * BB * NN) / 8, TPB>>>(desc_src, desc_dst);

    dim3 grid(NN / BN, BB);   // 16 x 8 = 128 CTAs
    match_kernel<<<grid, TPB, SMEM_TOTAL>>>(points_dst, out);
}

// round 13
// speedup vs baseline: 1.2495x; 1.0082x over previous
#include <cuda_runtime.h>
#include <cstdint>
#include <math.h>

#define BB 8
#define NN 2048
#define MM 2048
#define DD 256

#define TPB 512                 // 16 warps: 4x4 warp grid over the 128x128 tile
#define PACK_TPB 256
#define BN  128                 // src rows per CTA (MMA M)
#define BMT 128                 // dst rows per m-tile
#define KC  32
#define NMT (MM / BMT)          // 16
#define NCHUNK (DD / KC)        // 8
#define TOTC (NMT * NCHUNK)     // 128

#define PKF 512                 // packed floats per row: 256 k * (hi+lo)

// 256B rows; 16B units XOR-swizzled: su = u ^ ((row&1)<<2)  (proven conflict-free)
#define SWU(row, u) (((row) << 8) + ((((u) ^ (((row) & 1) << 2))) << 4))
#define ATILEB (128 * 256)              // 32768 B per tile
#define BUFB   (2 * ATILEB)             // 65536 B per stage
#define NSTAGE 3
#define RED_OFF (NSTAGE * BUFB)         // 196608
#define SMEM_TOTAL (NSTAGE * BUFB + 4096)   // 200704 B -> 1 CTA/SM

__device__ float g_ixn[BB * NN];
__device__ float g_iyn[BB * MM];
__device__ float g_psrc[BB * NN * PKF];
__device__ float g_pdst[BB * MM * PKF];

static __device__ __forceinline__ uint32_t smem_u32(const void* p) {
    uint32_t a;
    asm("{ .reg .u64 t; cvta.to.shared.u64 t, %1; cvt.u32.u64 %0, t; }" : "=r"(a) : "l"(p));
    return a;
}
static __device__ __forceinline__ void cpasync16(uint32_t saddr, const void* g) {
    asm volatile("cp.async.cg.shared.global [%0], [%1], 16;" :: "r"(saddr), "l"(g));
}
static __device__ __forceinline__ void cp_commit() {
    asm volatile("cp.async.commit_group;" ::: "memory");
}
template <int N>
static __device__ __forceinline__ void cp_wait() {
    asm volatile("cp.async.wait_group %0;" :: "n"(N) : "memory");
}
static __device__ __forceinline__ void split1(float x, float& h, float& l) {
    uint32_t hh;
    asm("cvt.rna.tf32.f32 %0, %1;" : "=r"(hh) : "f"(x));
    h = __uint_as_float(hh);
    float r = x - h;
    uint32_t ll;
    asm("cvt.rna.tf32.f32 %0, %1;" : "=r"(ll) : "f"(r));
    l = __uint_as_float(ll);
}
static __device__ __forceinline__ void mma8(float* d, const uint32_t* a, const uint32_t* b) {
    asm volatile(
        "mma.sync.aligned.m16n8k8.row.col.f32.tf32.tf32.f32 "
        "{%0,%1,%2,%3}, {%4,%5,%6,%7}, {%8,%9}, {%0,%1,%2,%3};"
        : "+f"(d[0]), "+f"(d[1]), "+f"(d[2]), "+f"(d[3])
        : "r"(a[0]), "r"(a[1]), "r"(a[2]), "r"(a[3]), "r"(b[0]), "r"(b[1]));
}

// Prepass: inverse L2 norm + packed hi/lo tf32 in MMA fragment order.
__global__ __launch_bounds__(PACK_TPB)
void pack_kernel(const float* __restrict__ src, const float* __restrict__ dst) {
    __shared__ float stage[8][264];
    const int wid = threadIdx.x >> 5, lane = threadIdx.x & 31;
    int row = blockIdx.x * 8 + wid;
    const float* p;
    float* onorm;
    float* pk;
    int r;
    if (row < BB * NN) { p = src; onorm = g_ixn; pk = g_psrc; r = row; }
    else               { p = dst; onorm = g_iyn; pk = g_pdst; r = row - BB * NN; }

    const float4* v = (const float4*)(p + (size_t)r * DD);
    float4 x0 = v[lane * 2], x1 = v[lane * 2 + 1];
    *(float4*)&stage[wid][lane * 8]     = x0;
    *(float4*)&stage[wid][lane * 8 + 4] = x1;
    float s = x0.x * x0.x + x0.y * x0.y + x0.z * x0.z + x0.w * x0.w
            + x1.x * x1.x + x1.y * x1.y + x1.z * x1.z + x1.w * x1.w;
    #pragma unroll
    for (int off = 16; off; off >>= 1) s += __shfl_xor_sync(0xffffffffu, s, off);
    if (lane == 0) onorm[r] = 1.0f / sqrtf(s);
    __syncwarp();

    float4* outp = (float4*)(pk + (size_t)r * PKF);
    #pragma unroll
    for (int i = 0; i < 4; i++) {
        int u = lane + 32 * i;
        int c = u >> 4, q = u & 15;
        int ks = q >> 2, g = q & 3;
        int k = c * 32 + ks * 8 + g;
        float h0, l0, h1, l1;
        split1(stage[wid][k],     h0, l0);
        split1(stage[wid][k + 4], h1, l1);
        outp[u] = make_float4(h0, h1, l0, l1);
    }
}

__global__ __launch_bounds__(TPB, 1)
void match_kernel(const float* __restrict__ pts, float* __restrict__ out) {
    extern __shared__ char sm[];
    const uint32_t sb = smem_u32(sm);
    const int tid = threadIdx.x;
    const int lane = tid & 31;
    const int wid  = tid >> 5;
    const int gid  = lane >> 2;
    const int tig  = lane & 3;
    const int wr   = wid & 3;    // row band: rows wr*32..+31
    const int wc   = wid >> 2;   // col band (0..3): cols wc*32..+31
    const int b  = blockIdx.y;
    const int n0 = blockIdx.x * BN;

    const float* gAp = g_psrc + ((size_t)b * NN + n0) * PKF;
    const float* gBp = g_pdst + (size_t)b * MM * PKF;

    auto issue = [&](int cc, int st) {
        const float* gB = gBp + (size_t)(cc >> 3) * BMT * PKF;
        const int ch = cc & 7;
        const uint32_t aBase = sb + st * BUFB;
        const uint32_t bBase = aBase + ATILEB;
        #pragma unroll
        for (int i = 0; i < 4; i++) {          // A: 128 rows x 16 units = 2048
            int lin = tid + i * TPB;
            int row = lin >> 4, u = lin & 15;
            cpasync16(aBase + SWU(row, u), gAp + (size_t)row * PKF + ch * 64 + u * 4);
        }
        #pragma unroll
        for (int i = 0; i < 4; i++) {          // B: 128 rows x 16 units
            int lin = tid + i * TPB;
            int row = lin >> 4, u = lin & 15;
            cpasync16(bBase + SWU(row, u), gB + (size_t)row * PKF + ch * 64 + u * 4);
        }
    };

    float acc[2][4][4];
    #pragma unroll
    for (int i = 0; i < 2; i++)
        #pragma unroll
        for (int j = 0; j < 4; j++)
            #pragma unroll
            for (int k = 0; k < 4; k++) acc[i][j][k] = 0.0f;

    float best[4];
    int   bidx[4];
    #pragma unroll
    for (int j = 0; j < 4; j++) { best[j] = -1e30f; bidx[j] = 0; }

    issue(0, 0); cp_commit();
    issue(1, 1); cp_commit();

    int st = 0;
    #pragma unroll 1
    for (int cc = 0; cc < TOTC; cc++) {
        cp_wait<1>();
        __syncthreads();           // publish chunk cc; proves cc-1 reads finished

        {                          // prefetch cc+2 into stage freed by cc-1
            int st2 = st + 2; if (st2 >= NSTAGE) st2 -= NSTAGE;
            if (cc + 2 < TOTC) issue(cc + 2, st2);
            cp_commit();
        }

        const char* A  = sm + st * BUFB;
        const char* Bm = A + ATILEB;

        #pragma unroll
        for (int ks = 0; ks < 4; ks++) {
            const int u = ks * 4 + tig;
            uint32_t aH[2][4], aL[2][4];
            #pragma unroll
            for (int mt2 = 0; mt2 < 2; mt2++) {
                int r0 = wr * 32 + mt2 * 16 + gid;
                float4 v0 = *(const float4*)(A + SWU(r0, u));
                float4 v1 = *(const float4*)(A + SWU(r0 + 8, u));
                aH[mt2][0] = __float_as_uint(v0.x);
                aH[mt2][1] = __float_as_uint(v1.x);
                aH[mt2][2] = __float_as_uint(v0.y);
                aH[mt2][3] = __float_as_uint(v1.y);
                aL[mt2][0] = __float_as_uint(v0.z);
                aL[mt2][1] = __float_as_uint(v1.z);
                aL[mt2][2] = __float_as_uint(v0.w);
                aL[mt2][3] = __float_as_uint(v1.w);
            }
            uint32_t bH[4][2], bL[4][2];
            #pragma unroll
            for (int nt = 0; nt < 4; nt++) {
                int rn = wc * 32 + nt * 8 + gid;
                float4 v = *(const float4*)(Bm + SWU(rn, u));
                bH[nt][0] = __float_as_uint(v.x);
                bH[nt][1] = __float_as_uint(v.y);
                bL[nt][0] = __float_as_uint(v.z);
                bL[nt][1] = __float_as_uint(v.w);
            }
            #pragma unroll
            for (int mt2 = 0; mt2 < 2; mt2++)
                #pragma unroll
                for (int nt = 0; nt < 4; nt++) {
                    mma8(acc[mt2][nt], aH[mt2], bH[nt]);   // hh
                    mma8(acc[mt2][nt], aH[mt2], bL[nt]);   // hl
                    mma8(acc[mt2][nt], aL[mt2], bH[nt]);   // lh
                }
        }

        if ((cc & 7) == 7) {
            const int mt = cc >> 3;
            const int mbase = mt * BMT + wc * 32;
            const float* iy = g_iyn + b * MM + mbase;
            #pragma unroll
            for (int nt = 0; nt < 4; nt++) {
                float2 y2 = *(const float2*)(iy + nt * 8 + 2 * tig);
                int m0 = mbase + nt * 8 + 2 * tig;
                #pragma unroll
                for (int mt2 = 0; mt2 < 2; mt2++) {
                    float v0 = acc[mt2][nt][0] * y2.x;
                    float v1 = acc[mt2][nt][1] * y2.y;
                    float v2 = acc[mt2][nt][2] * y2.x;
                    float v3 = acc[mt2][nt][3] * y2.y;
                    int j0 = mt2 * 2, j1 = mt2 * 2 + 1;
                    if (v0 > best[j0]) { best[j0] = v0; bidx[j0] = m0; }
                    if (v1 > best[j0]) { best[j0] = v1; bidx[j0] = m0 + 1; }
                    if (v2 > best[j1]) { best[j1] = v2; bidx[j1] = m0; }
                    if (v3 > best[j1]) { best[j1] = v3; bidx[j1] = m0 + 1; }
                    acc[mt2][nt][0] = 0.0f; acc[mt2][nt][1] = 0.0f;
                    acc[mt2][nt][2] = 0.0f; acc[mt2][nt][3] = 0.0f;
                }
            }
        }

        if (++st == NSTAGE) st = 0;
    }
    __syncthreads();

    // reduce across quad lanes, stash per col-band (4 bands), merge
    float* sval = (float*)(sm + RED_OFF);
    int*   sidx = (int*)(sm + RED_OFF + 4 * 128 * 4);
    #pragma unroll
    for (int j = 0; j < 4; j++) {
        float v = best[j];
        int   id = bidx[j];
        #pragma unroll
        for (int off = 1; off < 4; off <<= 1) {
            float ov = __shfl_xor_sync(0xffffffffu, v, off);
            int   oi = __shfl_xor_sync(0xffffffffu, id, off);
            if (ov > v || (ov == v && oi < id)) { v = ov; id = oi; }
        }
        if (tig == 0) {
            int r = wr * 32 + (j >> 1) * 16 + (j & 1) * 8 + gid;   // 0..127
            sval[wc * 128 + r] = v;
            sidx[wc * 128 + r] = id;
        }
    }
    __syncthreads();

    if (tid < 128) {
        int r = tid;
        float v = sval[r];
        int id = sidx[r];
        #pragma unroll
        for (int wb = 1; wb < 4; wb++) {
            float ov = sval[wb * 128 + r];
            int   oi = sidx[wb * 128 + r];
            if (ov > v || (ov == v && oi < id)) { v = ov; id = oi; }
        }
        int n = n0 + r;
        float conf = v * g_ixn[b * NN + n];
        size_t ob = (size_t)b * NN + n;
        out[ob * 2]     = pts[((size_t)b * MM + id) * 2];
        out[ob * 2 + 1] = pts[((size_t)b * MM + id) * 2 + 1];
        out[(size_t)BB * NN * 2 + ob] = conf;
    }
}

extern "C" void kernel_launch(void* const* d_in, const int* in_sizes, int n_in,
                              void* d_out, int out_size) {
    const float* desc_src = (const float*)d_in[0];
    const float* desc_dst = (const float*)d_in[1];
    const float* points_dst = (const float*)d_in[2];
    float* out = (float*)d_out;

    cudaFuncSetAttribute(match_kernel, cudaFuncAttributeMaxDynamicSharedMemorySize,
                         SMEM_TOTAL);

    pack_kernel<<<(2 * BB * NN) / 8, PACK_TPB>>>(desc_src, desc_dst);

    dim3 grid(NN / BN, BB);   // 16 x 8 = 128 CTAs
    match_kernel<<<grid, TPB, SMEM_TOTAL>>>(points_dst, out);
}

// round 16
// speedup vs baseline: 2.4397x; 1.9525x over previous
#include <cuda_runtime.h>
#include <cuda_fp16.h>
#include <cstdint>
#include <math.h>

#define BB 8
#define NN 2048
#define MM 2048
#define DD 256

#define TPB 512                 // 16 warps: 4x4 warp grid over the 128x128 tile
#define PACK_TPB 256
#define BN  128
#define BMT 128
#define KC  64                  // k per chunk (4 x k16 steps)
#define NMT (MM / BMT)          // 16
#define NCHPT (DD / KC)         // 4 chunks per m-tile
#define TOTC (NMT * NCHPT)      // 64

#define PKF 256                 // packed floats per row: 256 k * (hi+lo) fp16 = 1024B

// 256B rows; 16B units XOR-swizzled: su = u ^ ((row&1)<<2)  (proven conflict-free)
#define SWU(row, u) (((row) << 8) + ((((u) ^ (((row) & 1) << 2))) << 4))
#define ATILEB (128 * 256)              // 32768 B per tile (128 rows x 256B)
#define BUFB   (2 * ATILEB)             // 65536 B per stage
#define NSTAGE 3
#define RED_OFF (NSTAGE * BUFB)
#define SMEM_TOTAL (NSTAGE * BUFB + 4096)   // 200704 B -> 1 CTA/SM

__device__ float g_ixn[BB * NN];
__device__ float g_iyn[BB * MM];
__device__ float g_psrc[BB * NN * PKF];   // packed hi/lo fp16 (as floats4 units)
__device__ float g_pdst[BB * MM * PKF];

static __device__ __forceinline__ uint32_t smem_u32(const void* p) {
    uint32_t a;
    asm("{ .reg .u64 t; cvta.to.shared.u64 t, %1; cvt.u32.u64 %0, t; }" : "=r"(a) : "l"(p));
    return a;
}
static __device__ __forceinline__ void cpasync16(uint32_t saddr, const void* g) {
    asm volatile("cp.async.cg.shared.global [%0], [%1], 16;" :: "r"(saddr), "l"(g));
}
static __device__ __forceinline__ void cp_commit() {
    asm volatile("cp.async.commit_group;" ::: "memory");
}
template <int N>
static __device__ __forceinline__ void cp_wait() {
    asm volatile("cp.async.wait_group %0;" :: "n"(N) : "memory");
}
// fp16 m16n8k16, fp32 accumulate
static __device__ __forceinline__ void mma16(float* d, const uint32_t* a, const uint32_t* b) {
    asm volatile(
        "mma.sync.aligned.m16n8k16.row.col.f32.f16.f16.f32 "
        "{%0,%1,%2,%3}, {%4,%5,%6,%7}, {%8,%9}, {%0,%1,%2,%3};"
        : "+f"(d[0]), "+f"(d[1]), "+f"(d[2]), "+f"(d[3])
        : "r"(a[0]), "r"(a[1]), "r"(a[2]), "r"(a[3]), "r"(b[0]), "r"(b[1]));
}

// Prepass: inverse L2 norm + packed hi/lo fp16 in m16n8k16 fragment order.
// Unit u (16B) of a row: s=u>>2 (k16 step), t=u&3; kb=16s+2t;
// unit = {hi2(kb,kb+1), hi2(kb+8,kb+9), lo2(kb,kb+1), lo2(kb+8,kb+9)}
__global__ __launch_bounds__(PACK_TPB)
void pack_kernel(const float* __restrict__ src, const float* __restrict__ dst) {
    __shared__ float stage[8][264];
    const int wid = threadIdx.x >> 5, lane = threadIdx.x & 31;
    int row = blockIdx.x * 8 + wid;
    const float* p;
    float* onorm;
    float* pk;
    int r;
    if (row < BB * NN) { p = src; onorm = g_ixn; pk = g_psrc; r = row; }
    else               { p = dst; onorm = g_iyn; pk = g_pdst; r = row - BB * NN; }

    const float4* v = (const float4*)(p + (size_t)r * DD);
    float4 x0 = v[lane * 2], x1 = v[lane * 2 + 1];
    *(float4*)&stage[wid][lane * 8]     = x0;
    *(float4*)&stage[wid][lane * 8 + 4] = x1;
    float s = x0.x * x0.x + x0.y * x0.y + x0.z * x0.z + x0.w * x0.w
            + x1.x * x1.x + x1.y * x1.y + x1.z * x1.z + x1.w * x1.w;
    #pragma unroll
    for (int off = 16; off; off >>= 1) s += __shfl_xor_sync(0xffffffffu, s, off);
    if (lane == 0) onorm[r] = 1.0f / sqrtf(s);
    __syncwarp();

    float4* outp = (float4*)(pk + (size_t)r * PKF);
    #pragma unroll
    for (int i = 0; i < 2; i++) {
        int u = lane + 32 * i;          // 0..63 units
        int st_ = u >> 2, t = u & 3;
        int kb = 16 * st_ + 2 * t;
        float x[4] = { stage[wid][kb], stage[wid][kb + 1],
                       stage[wid][kb + 8], stage[wid][kb + 9] };
        __half h[4], l[4];
        #pragma unroll
        for (int j = 0; j < 4; j++) {
            h[j] = __float2half_rn(x[j]);
            l[j] = __float2half_rn(x[j] - __half2float(h[j]));
        }
        float4 o;
        o.x = __uint_as_float((uint32_t)__half_as_ushort(h[0]) |
                              ((uint32_t)__half_as_ushort(h[1]) << 16));
        o.y = __uint_as_float((uint32_t)__half_as_ushort(h[2]) |
                              ((uint32_t)__half_as_ushort(h[3]) << 16));
        o.z = __uint_as_float((uint32_t)__half_as_ushort(l[0]) |
                              ((uint32_t)__half_as_ushort(l[1]) << 16));
        o.w = __uint_as_float((uint32_t)__half_as_ushort(l[2]) |
                              ((uint32_t)__half_as_ushort(l[3]) << 16));
        outp[u] = o;
    }
}

__global__ __launch_bounds__(TPB, 1)
void match_kernel(const float* __restrict__ pts, float* __restrict__ out) {
    extern __shared__ char sm[];
    const uint32_t sb = smem_u32(sm);
    const int tid = threadIdx.x;
    const int lane = tid & 31;
    const int wid  = tid >> 5;
    const int gid  = lane >> 2;
    const int tig  = lane & 3;
    const int wr   = wid & 3;    // row band: rows wr*32..+31
    const int wc   = wid >> 2;   // col band (0..3): cols wc*32..+31
    const int b  = blockIdx.y;
    const int n0 = blockIdx.x * BN;

    const float* gAp = g_psrc + ((size_t)b * NN + n0) * PKF;
    const float* gBp = g_pdst + (size_t)b * MM * PKF;

    auto issue = [&](int cc, int st) {
        const float* gB = gBp + (size_t)(cc >> 2) * BMT * PKF;
        const int ch = cc & 3;
        const uint32_t aBase = sb + st * BUFB;
        const uint32_t bBase = aBase + ATILEB;
        #pragma unroll
        for (int i = 0; i < 4; i++) {          // A: 128 rows x 16 units
            int lin = tid + i * TPB;
            int row = lin >> 4, u = lin & 15;
            cpasync16(aBase + SWU(row, u), gAp + (size_t)row * PKF + ch * 64 + u * 4);
        }
        #pragma unroll
        for (int i = 0; i < 4; i++) {          // B: 128 rows x 16 units
            int lin = tid + i * TPB;
            int row = lin >> 4, u = lin & 15;
            cpasync16(bBase + SWU(row, u), gB + (size_t)row * PKF + ch * 64 + u * 4);
        }
    };

    float acc[2][4][4];
    #pragma unroll
    for (int i = 0; i < 2; i++)
        #pragma unroll
        for (int j = 0; j < 4; j++)
            #pragma unroll
            for (int k = 0; k < 4; k++) acc[i][j][k] = 0.0f;

    float best[4];
    int   bidx[4];
    #pragma unroll
    for (int j = 0; j < 4; j++) { best[j] = -1e30f; bidx[j] = 0; }

    issue(0, 0); cp_commit();
    issue(1, 1); cp_commit();

    int st = 0;
    #pragma unroll 1
    for (int cc = 0; cc < TOTC; cc++) {
        cp_wait<1>();
        __syncthreads();           // publish chunk cc; proves cc-1 reads finished

        {                          // prefetch cc+2 into stage freed by cc-1
            int st2 = st + 2; if (st2 >= NSTAGE) st2 -= NSTAGE;
            if (cc + 2 < TOTC) issue(cc + 2, st2);
            cp_commit();
        }

        const char* A  = sm + st * BUFB;
        const char* Bm = A + ATILEB;

        #pragma unroll
        for (int ks = 0; ks < 4; ks++) {       // 4 x k16 steps
            const int u = ks * 4 + tig;
            uint32_t aH[2][4], aL[2][4];
            #pragma unroll
            for (int mt2 = 0; mt2 < 2; mt2++) {
                int r0 = wr * 32 + mt2 * 16 + gid;
                float4 v0 = *(const float4*)(A + SWU(r0, u));
                float4 v1 = *(const float4*)(A + SWU(r0 + 8, u));
                aH[mt2][0] = __float_as_uint(v0.x);   // row g,   k low pair
                aH[mt2][1] = __float_as_uint(v1.x);   // row g+8, k low pair
                aH[mt2][2] = __float_as_uint(v0.y);   // row g,   k high pair
                aH[mt2][3] = __float_as_uint(v1.y);   // row g+8, k high pair
                aL[mt2][0] = __float_as_uint(v0.z);
                aL[mt2][1] = __float_as_uint(v1.z);
                aL[mt2][2] = __float_as_uint(v0.w);
                aL[mt2][3] = __float_as_uint(v1.w);
            }
            uint32_t bH[4][2], bL[4][2];
            #pragma unroll
            for (int nt = 0; nt < 4; nt++) {
                int rn = wc * 32 + nt * 8 + gid;
                float4 v = *(const float4*)(Bm + SWU(rn, u));
                bH[nt][0] = __float_as_uint(v.x);
                bH[nt][1] = __float_as_uint(v.y);
                bL[nt][0] = __float_as_uint(v.z);
                bL[nt][1] = __float_as_uint(v.w);
            }
            #pragma unroll
            for (int mt2 = 0; mt2 < 2; mt2++)
                #pragma unroll
                for (int nt = 0; nt < 4; nt++) {
                    mma16(acc[mt2][nt], aH[mt2], bH[nt]);   // hh
                    mma16(acc[mt2][nt], aH[mt2], bL[nt]);   // hl
                    mma16(acc[mt2][nt], aL[mt2], bH[nt]);   // lh
                }
        }

        if ((cc & 3) == 3) {
            const int mt = cc >> 2;
            const int mbase = mt * BMT + wc * 32;
            const float* iy = g_iyn + b * MM + mbase;
            #pragma unroll
            for (int nt = 0; nt < 4; nt++) {
                float2 y2 = *(const float2*)(iy + nt * 8 + 2 * tig);
                int m0 = mbase + nt * 8 + 2 * tig;
                #pragma unroll
                for (int mt2 = 0; mt2 < 2; mt2++) {
                    float v0 = acc[mt2][nt][0] * y2.x;
                    float v1 = acc[mt2][nt][1] * y2.y;
                    float v2 = acc[mt2][nt][2] * y2.x;
                    float v3 = acc[mt2][nt][3] * y2.y;
                    int j0 = mt2 * 2, j1 = mt2 * 2 + 1;
                    if (v0 > best[j0]) { best[j0] = v0; bidx[j0] = m0; }
                    if (v1 > best[j0]) { best[j0] = v1; bidx[j0] = m0 + 1; }
                    if (v2 > best[j1]) { best[j1] = v2; bidx[j1] = m0; }
                    if (v3 > best[j1]) { best[j1] = v3; bidx[j1] = m0 + 1; }
                    acc[mt2][nt][0] = 0.0f; acc[mt2][nt][1] = 0.0f;
                    acc[mt2][nt][2] = 0.0f; acc[mt2][nt][3] = 0.0f;
                }
            }
        }

        if (++st == NSTAGE) st = 0;
    }
    __syncthreads();

    // reduce across quad lanes, stash per col-band (4 bands), merge
    float* sval = (float*)(sm + RED_OFF);
    int*   sidx = (int*)(sm + RED_OFF + 4 * 128 * 4);
    #pragma unroll
    for (int j = 0; j < 4; j++) {
        float v = best[j];
        int   id = bidx[j];
        #pragma unroll
        for (int off = 1; off < 4; off <<= 1) {
            float ov = __shfl_xor_sync(0xffffffffu, v, off);
            int   oi = __shfl_xor_sync(0xffffffffu, id, off);
            if (ov > v || (ov == v && oi < id)) { v = ov; id = oi; }
        }
        if (tig == 0) {
            int r = wr * 32 + (j >> 1) * 16 + (j & 1) * 8 + gid;   // 0..127
            sval[wc * 128 + r] = v;
            sidx[wc * 128 + r] = id;
        }
    }
    __syncthreads();

    if (tid < 128) {
        int r = tid;
        float v = sval[r];
        int id = sidx[r];
        #pragma unroll
        for (int wb = 1; wb < 4; wb++) {
            float ov = sval[wb * 128 + r];
            int   oi = sidx[wb * 128 + r];
            if (ov > v || (ov == v && oi < id)) { v = ov; id = oi; }
        }
        int n = n0 + r;
        float conf = v * g_ixn[b * NN + n];
        size_t ob = (size_t)b * NN + n;
        out[ob * 2]     = pts[((size_t)b * MM + id) * 2];
        out[ob * 2 + 1] = pts[((size_t)b * MM + id) * 2 + 1];
        out[(size_t)BB * NN * 2 + ob] = conf;
    }
}

extern "C" void kernel_launch(void* const* d_in, const int* in_sizes, int n_in,
                              void* d_out, int out_size) {
    const float* desc_src = (const float*)d_in[0];
    const float* desc_dst = (const float*)d_in[1];
    const float* points_dst = (const float*)d_in[2];
    float* out = (float*)d_out;

    cudaFuncSetAttribute(match_kernel, cudaFuncAttributeMaxDynamicSharedMemorySize,
                         SMEM_TOTAL);

    pack_kernel<<<(2 * BB * NN) / 8, PACK_TPB>>>(desc_src, desc_dst);

    dim3 grid(NN / BN, BB);   // 16 x 8 = 128 CTAs
    match_kernel<<<grid, TPB, SMEM_TOTAL>>>(points_dst, out);
}